// round 6
// baseline (speedup 1.0000x reference)
#include <cuda_runtime.h>

#define TOK_TOTAL 65536
#define TOK_HALF  32768
#define HD 1024
#define NLEV 4

// Scratch (static device globals; no runtime allocation allowed)
__device__ float g_H[(size_t)TOK_TOTAL * HD];    // 256MB hidden activations
__device__ float g_logits[TOK_TOTAL * NLEV];     // 1MB
__device__ int   g_idx[NLEV * TOK_TOTAL];        // 1MB bucketed token ids
__device__ int   g_count[NLEV];

struct CompParams {
    const float* keys;
    const float* values;
    const float* w1[NLEV];
    const float* b1[NLEV];
    const float* w2[NLEV];
    const float* b2[NLEV];
    float* out;
};

// ---------------------------------------------------------------------------
// Shared SGEMM mainloop: BM=BN=128, BK=8, 256 threads, 8x8 microtile.
// a_ptr: per-thread pointer to A[row, kA] (row fixed, advanced by k0).
// b_ptr: B + n0 (element (k, n_local) at b_ptr[k*ldb + n_local]).
// ---------------------------------------------------------------------------
__device__ __forceinline__ void gemm_mainloop(
    const float* a_ptr, const float* b_ptr, int ldb, int K,
    float (&c)[8][8], float (*As)[128], float (*Bs)[128])
{
    const int tid  = threadIdx.x;
    const int rowA = tid & 127;
    const int kA   = (tid >> 7) << 2;     (void)kA;
    const int kB   = tid >> 5;
    const int nB   = (tid & 31) << 2;
    const int tx   = tid & 15;
    const int ty   = tid >> 4;

    float4 av = *(const float4*)(a_ptr);
    float4 bv = *(const float4*)(b_ptr + (size_t)kB * ldb + nB);

    for (int k0 = 0; k0 < K; k0 += 8) {
        __syncthreads();
        As[((tid >> 7) << 2) + 0][rowA] = av.x;
        As[((tid >> 7) << 2) + 1][rowA] = av.y;
        As[((tid >> 7) << 2) + 2][rowA] = av.z;
        As[((tid >> 7) << 2) + 3][rowA] = av.w;
        *(float4*)&Bs[kB][nB] = bv;
        __syncthreads();
        if (k0 + 8 < K) {
            av = *(const float4*)(a_ptr + k0 + 8);
            bv = *(const float4*)(b_ptr + (size_t)(k0 + 8 + kB) * ldb + nB);
        }
#pragma unroll
        for (int kk = 0; kk < 8; kk++) {
            float4 a0 = *(float4*)&As[kk][ty * 4];
            float4 a1 = *(float4*)&As[kk][64 + ty * 4];
            float4 b0 = *(float4*)&Bs[kk][tx * 4];
            float4 b1 = *(float4*)&Bs[kk][64 + tx * 4];
            float a[8] = {a0.x, a0.y, a0.z, a0.w, a1.x, a1.y, a1.z, a1.w};
            float b[8] = {b0.x, b0.y, b0.z, b0.w, b1.x, b1.y, b1.z, b1.w};
#pragma unroll
            for (int i = 0; i < 8; i++)
#pragma unroll
                for (int j = 0; j < 8; j++)
                    c[i][j] = fmaf(a[i], b[j], c[i][j]);
        }
    }
}

__device__ __forceinline__ int rmap(int ty, int i) {
    return (i < 4) ? (ty * 4 + i) : (64 + ty * 4 + (i - 4));
}
__device__ __forceinline__ int cmap(int tx, int j) {
    return (j < 4) ? (tx * 4 + j) : (64 + tx * 4 + (j - 4));
}

// ---------------------------------------------------------------------------
// Zero scratch (logits + bucket counts)
// ---------------------------------------------------------------------------
__global__ void zero_kernel() {
    int i = blockIdx.x * 256 + threadIdx.x;
    if (i < TOK_TOTAL * NLEV) g_logits[i] = 0.f;
    if (i < NLEV) g_count[i] = 0;
}

// ---------------------------------------------------------------------------
// Predictor: C = X @ W1cat (N=1024 = 4 levels x 256), epilogue reduces
// relu(c + b1) * w2 over columns of each level-segment into g_logits.
// grid (8, 256, 2): z=0 keys, z=1 values.
// ---------------------------------------------------------------------------
__global__ __launch_bounds__(256, 2) void predictor_kernel(
    const float* __restrict__ keys, const float* __restrict__ values,
    const float* __restrict__ Pw1, const float* __restrict__ Pb1,
    const float* __restrict__ Pw2)
{
    __shared__ float As[8][128], Bs[8][128];
    const int tid = threadIdx.x;
    const int bx = blockIdx.x, by = blockIdx.y, bz = blockIdx.z;
    const float* X = bz ? values : keys;
    const int tokbase = bz * TOK_HALF + by * 128;

    const int n0  = bx * 128;
    const int lev = n0 >> 8;           // 128-col tile lies within one level
    const int jc  = n0 & 255;
    const float* Bp = Pw1 + (size_t)lev * HD * 256 + jc;   // [k][j], ldb=256

    const int rowA = tid & 127, kA = (tid >> 7) << 2;
    const float* a_ptr = X + (size_t)(by * 128 + rowA) * HD + kA;

    float c[8][8];
#pragma unroll
    for (int i = 0; i < 8; i++)
#pragma unroll
        for (int j = 0; j < 8; j++) c[i][j] = 0.f;

    gemm_mainloop(a_ptr, Bp, 256, HD, c, As, Bs);

    const int tx = tid & 15, ty = tid >> 4;
    float w2v[8], b1v[8];
#pragma unroll
    for (int j = 0; j < 8; j++) {
        int n = n0 + cmap(tx, j);      // global col == flat index into Pb1/Pw2
        w2v[j] = Pw2[n];
        b1v[j] = Pb1[n];
    }
    float part[8];
#pragma unroll
    for (int i = 0; i < 8; i++) {
        float s = 0.f;
#pragma unroll
        for (int j = 0; j < 8; j++)
            s += fmaxf(c[i][j] + b1v[j], 0.f) * w2v[j];
        part[i] = s;
    }
    for (int off = 8; off >= 1; off >>= 1)
#pragma unroll
        for (int i = 0; i < 8; i++)
            part[i] += __shfl_xor_sync(0xffffffffu, part[i], off, 16);
    if (tx == 0) {
#pragma unroll
        for (int i = 0; i < 8; i++) {
            int r = rmap(ty, i);
            atomicAdd(&g_logits[(size_t)(tokbase + r) * NLEV + lev], part[i]);
        }
    }
}

// ---------------------------------------------------------------------------
// Argmax (sigmoid is monotone -> argmax of raw logits) + bucket compaction.
// ---------------------------------------------------------------------------
__global__ void argmax_kernel(const float* __restrict__ Pb2) {
    int t = blockIdx.x * 256 + threadIdx.x;
    if (t >= TOK_TOTAL) return;
    float best = g_logits[t * NLEV] + Pb2[0];
    int bl = 0;
#pragma unroll
    for (int l = 1; l < NLEV; l++) {
        float v = g_logits[t * NLEV + l] + Pb2[l];
        if (v > best) { best = v; bl = l; }   // strict > = first-max tiebreak
    }
    int p = atomicAdd(&g_count[bl], 1);
    g_idx[bl * TOK_TOTAL + p] = t;
}

// ---------------------------------------------------------------------------
// Stage A: H = relu(Xg @ w1_l + b1_l). grid (8, 512, 4), early-exit on
// d/count. A-rows gathered by bucket; H stored by token id (ld=1024).
// ---------------------------------------------------------------------------
__global__ __launch_bounds__(256, 2) void stageA_kernel(CompParams P) {
    const int lev = blockIdx.z;
    const int d = HD >> lev;
    const int n0 = blockIdx.x * 128;
    if (n0 >= d) return;
    const int cnt = g_count[lev];
    const int m0 = blockIdx.y * 128;
    if (m0 >= cnt) return;

    __shared__ float As[8][128], Bs[8][128];
    const int tid = threadIdx.x;
    const int rowA = tid & 127, kA = (tid >> 7) << 2;
    int rload = m0 + rowA; if (rload > cnt - 1) rload = cnt - 1;
    const int tl = g_idx[lev * TOK_TOTAL + rload];
    const float* arow = (tl < TOK_HALF)
        ? (P.keys + (size_t)tl * HD)
        : (P.values + (size_t)(tl - TOK_HALF) * HD);

    float c[8][8];
#pragma unroll
    for (int i = 0; i < 8; i++)
#pragma unroll
        for (int j = 0; j < 8; j++) c[i][j] = 0.f;

    gemm_mainloop(arow + kA, P.w1[lev] + n0, d, HD, c, As, Bs);

    const int tx = tid & 15, ty = tid >> 4;
    const float* b1 = P.b1[lev] + n0;
    float b1v[8];
#pragma unroll
    for (int j = 0; j < 8; j++) b1v[j] = b1[cmap(tx, j)];

#pragma unroll
    for (int i = 0; i < 8; i++) {
        int r = m0 + rmap(ty, i);
        if (r < cnt) {
            int t = g_idx[lev * TOK_TOTAL + r];
            float* dst = g_H + (size_t)t * HD + n0;
            float4 v0, v1;
            v0.x = fmaxf(c[i][0] + b1v[0], 0.f);
            v0.y = fmaxf(c[i][1] + b1v[1], 0.f);
            v0.z = fmaxf(c[i][2] + b1v[2], 0.f);
            v0.w = fmaxf(c[i][3] + b1v[3], 0.f);
            v1.x = fmaxf(c[i][4] + b1v[4], 0.f);
            v1.y = fmaxf(c[i][5] + b1v[5], 0.f);
            v1.z = fmaxf(c[i][6] + b1v[6], 0.f);
            v1.w = fmaxf(c[i][7] + b1v[7], 0.f);
            *(float4*)(dst + tx * 4)      = v0;
            *(float4*)(dst + 64 + tx * 4) = v1;
        }
    }
}

// ---------------------------------------------------------------------------
// Stage B: out = H @ w2_l + b2_l, scattered to out rows by token id.
// out layout: [keys_out | values_out] -> token t maps to out + t*1024.
// ---------------------------------------------------------------------------
__global__ __launch_bounds__(256, 2) void stageB_kernel(CompParams P) {
    const int lev = blockIdx.z;
    const int d = HD >> lev;               // K dimension
    const int n0 = blockIdx.x * 128;       // N = 1024
    const int cnt = g_count[lev];
    const int m0 = blockIdx.y * 128;
    if (m0 >= cnt) return;

    __shared__ float As[8][128], Bs[8][128];
    const int tid = threadIdx.x;
    const int rowA = tid & 127, kA = (tid >> 7) << 2;
    int rload = m0 + rowA; if (rload > cnt - 1) rload = cnt - 1;
    const int tl = g_idx[lev * TOK_TOTAL + rload];

    float c[8][8];
#pragma unroll
    for (int i = 0; i < 8; i++)
#pragma unroll
        for (int j = 0; j < 8; j++) c[i][j] = 0.f;

    gemm_mainloop(g_H + (size_t)tl * HD + kA, P.w2[lev] + n0, HD, d, c, As, Bs);

    const int tx = tid & 15, ty = tid >> 4;
    const float* b2 = P.b2[lev] + n0;
    float b2v[8];
#pragma unroll
    for (int j = 0; j < 8; j++) b2v[j] = b2[cmap(tx, j)];

#pragma unroll
    for (int i = 0; i < 8; i++) {
        int r = m0 + rmap(ty, i);
        if (r < cnt) {
            int t = g_idx[lev * TOK_TOTAL + r];
            float* dst = P.out + (size_t)t * HD + n0;
            float4 v0, v1;
            v0.x = c[i][0] + b2v[0];
            v0.y = c[i][1] + b2v[1];
            v0.z = c[i][2] + b2v[2];
            v0.w = c[i][3] + b2v[3];
            v1.x = c[i][4] + b2v[4];
            v1.y = c[i][5] + b2v[5];
            v1.z = c[i][6] + b2v[6];
            v1.w = c[i][7] + b2v[7];
            *(float4*)(dst + tx * 4)      = v0;
            *(float4*)(dst + 64 + tx * 4) = v1;
        }
    }
}

// ---------------------------------------------------------------------------
extern "C" void kernel_launch(void* const* d_in, const int* in_sizes, int n_in,
                              void* d_out, int out_size) {
    const float* keys   = (const float*)d_in[0];
    const float* values = (const float*)d_in[1];
    const float* Pw1    = (const float*)d_in[2];
    const float* Pb1    = (const float*)d_in[3];
    const float* Pw2    = (const float*)d_in[4];
    const float* Pb2    = (const float*)d_in[5];

    CompParams P;
    P.keys = keys; P.values = values;
    for (int l = 0; l < 4; l++) {
        P.w1[l] = (const float*)d_in[6 + l * 4 + 0];
        P.b1[l] = (const float*)d_in[6 + l * 4 + 1];
        P.w2[l] = (const float*)d_in[6 + l * 4 + 2];
        P.b2[l] = (const float*)d_in[6 + l * 4 + 3];
    }
    P.out = (float*)d_out;

    zero_kernel<<<(TOK_TOTAL * NLEV + 255) / 256, 256>>>();

    dim3 pgrid(8, 256, 2);                 // N-tiles, M-tiles (32768/128), keys|values
    predictor_kernel<<<pgrid, 256>>>(keys, values, Pw1, Pb1, Pw2);

    argmax_kernel<<<TOK_TOTAL / 256, 256>>>(Pb2);

    dim3 cgrid(8, 512, 4);                 // N-tiles, M-tiles (65536/128), levels
    stageA_kernel<<<cgrid, 256>>>(P);
    stageB_kernel<<<cgrid, 256>>>(P);
}

// round 7
// speedup vs baseline: 1.0005x; 1.0005x over previous
#include <cuda_runtime.h>

#define TOK_TOTAL 65536
#define TOK_HALF  32768
#define HD 1024
#define NLEV 4

// Scratch (static device globals; no runtime allocation allowed)
__device__ float g_H[(size_t)TOK_TOTAL * HD];    // 256MB hidden activations
__device__ float g_logits[TOK_TOTAL * NLEV];     // 1MB
__device__ int   g_idx[NLEV * TOK_TOTAL];        // 1MB bucketed token ids
__device__ int   g_count[NLEV];

struct CompParams {
    const float* keys;
    const float* values;
    const float* w1[NLEV];
    const float* b1[NLEV];
    const float* w2[NLEV];
    const float* b2[NLEV];
    float* out;
};

// ---------------------------------------------------------------------------
// Shared SGEMM mainloop: BM=BN=128, BK=8, 256 threads, 8x8 microtile.
// a_ptr: per-thread pointer to A[row, kA] (row fixed, advanced by k0).
// b_ptr: B + n0 (element (k, n_local) at b_ptr[k*ldb + n_local]).
// ---------------------------------------------------------------------------
__device__ __forceinline__ void gemm_mainloop(
    const float* a_ptr, const float* b_ptr, int ldb, int K,
    float (&c)[8][8], float (*As)[128], float (*Bs)[128])
{
    const int tid  = threadIdx.x;
    const int rowA = tid & 127;
    const int kA   = (tid >> 7) << 2;     (void)kA;
    const int kB   = tid >> 5;
    const int nB   = (tid & 31) << 2;
    const int tx   = tid & 15;
    const int ty   = tid >> 4;

    float4 av = *(const float4*)(a_ptr);
    float4 bv = *(const float4*)(b_ptr + (size_t)kB * ldb + nB);

    for (int k0 = 0; k0 < K; k0 += 8) {
        __syncthreads();
        As[((tid >> 7) << 2) + 0][rowA] = av.x;
        As[((tid >> 7) << 2) + 1][rowA] = av.y;
        As[((tid >> 7) << 2) + 2][rowA] = av.z;
        As[((tid >> 7) << 2) + 3][rowA] = av.w;
        *(float4*)&Bs[kB][nB] = bv;
        __syncthreads();
        if (k0 + 8 < K) {
            av = *(const float4*)(a_ptr + k0 + 8);
            bv = *(const float4*)(b_ptr + (size_t)(k0 + 8 + kB) * ldb + nB);
        }
#pragma unroll
        for (int kk = 0; kk < 8; kk++) {
            float4 a0 = *(float4*)&As[kk][ty * 4];
            float4 a1 = *(float4*)&As[kk][64 + ty * 4];
            float4 b0 = *(float4*)&Bs[kk][tx * 4];
            float4 b1 = *(float4*)&Bs[kk][64 + tx * 4];
            float a[8] = {a0.x, a0.y, a0.z, a0.w, a1.x, a1.y, a1.z, a1.w};
            float b[8] = {b0.x, b0.y, b0.z, b0.w, b1.x, b1.y, b1.z, b1.w};
#pragma unroll
            for (int i = 0; i < 8; i++)
#pragma unroll
                for (int j = 0; j < 8; j++)
                    c[i][j] = fmaf(a[i], b[j], c[i][j]);
        }
    }
}

__device__ __forceinline__ int rmap(int ty, int i) {
    return (i < 4) ? (ty * 4 + i) : (64 + ty * 4 + (i - 4));
}
__device__ __forceinline__ int cmap(int tx, int j) {
    return (j < 4) ? (tx * 4 + j) : (64 + tx * 4 + (j - 4));
}

// ---------------------------------------------------------------------------
// Zero scratch (logits + bucket counts)
// ---------------------------------------------------------------------------
__global__ void zero_kernel() {
    int i = blockIdx.x * 256 + threadIdx.x;
    if (i < TOK_TOTAL * NLEV) g_logits[i] = 0.f;
    if (i < NLEV) g_count[i] = 0;
}

// ---------------------------------------------------------------------------
// Predictor: C = X @ W1cat (N=1024 = 4 levels x 256), epilogue reduces
// relu(c + b1) * w2 over columns of each level-segment into g_logits.
// grid (8, 256, 2): z=0 keys, z=1 values.
// ---------------------------------------------------------------------------
__global__ __launch_bounds__(256, 2) void predictor_kernel(
    const float* __restrict__ keys, const float* __restrict__ values,
    const float* __restrict__ Pw1, const float* __restrict__ Pb1,
    const float* __restrict__ Pw2)
{
    __shared__ float As[8][128], Bs[8][128];
    const int tid = threadIdx.x;
    const int bx = blockIdx.x, by = blockIdx.y, bz = blockIdx.z;
    const float* X = bz ? values : keys;
    const int tokbase = bz * TOK_HALF + by * 128;

    const int n0  = bx * 128;
    const int lev = n0 >> 8;           // 128-col tile lies within one level
    const int jc  = n0 & 255;
    const float* Bp = Pw1 + (size_t)lev * HD * 256 + jc;   // [k][j], ldb=256

    const int rowA = tid & 127, kA = (tid >> 7) << 2;
    const float* a_ptr = X + (size_t)(by * 128 + rowA) * HD + kA;

    float c[8][8];
#pragma unroll
    for (int i = 0; i < 8; i++)
#pragma unroll
        for (int j = 0; j < 8; j++) c[i][j] = 0.f;

    gemm_mainloop(a_ptr, Bp, 256, HD, c, As, Bs);

    const int tx = tid & 15, ty = tid >> 4;
    float w2v[8], b1v[8];
#pragma unroll
    for (int j = 0; j < 8; j++) {
        int n = n0 + cmap(tx, j);      // global col == flat index into Pb1/Pw2
        w2v[j] = Pw2[n];
        b1v[j] = Pb1[n];
    }
    float part[8];
#pragma unroll
    for (int i = 0; i < 8; i++) {
        float s = 0.f;
#pragma unroll
        for (int j = 0; j < 8; j++)
            s += fmaxf(c[i][j] + b1v[j], 0.f) * w2v[j];
        part[i] = s;
    }
    for (int off = 8; off >= 1; off >>= 1)
#pragma unroll
        for (int i = 0; i < 8; i++)
            part[i] += __shfl_xor_sync(0xffffffffu, part[i], off, 16);
    if (tx == 0) {
#pragma unroll
        for (int i = 0; i < 8; i++) {
            int r = rmap(ty, i);
            atomicAdd(&g_logits[(size_t)(tokbase + r) * NLEV + lev], part[i]);
        }
    }
}

// ---------------------------------------------------------------------------
// Argmax (sigmoid is monotone -> argmax of raw logits) + bucket compaction.
// ---------------------------------------------------------------------------
__global__ void argmax_kernel(const float* __restrict__ Pb2) {
    int t = blockIdx.x * 256 + threadIdx.x;
    if (t >= TOK_TOTAL) return;
    float best = g_logits[t * NLEV] + Pb2[0];
    int bl = 0;
#pragma unroll
    for (int l = 1; l < NLEV; l++) {
        float v = g_logits[t * NLEV + l] + Pb2[l];
        if (v > best) { best = v; bl = l; }   // strict > = first-max tiebreak
    }
    int p = atomicAdd(&g_count[bl], 1);
    g_idx[bl * TOK_TOTAL + p] = t;
}

// ---------------------------------------------------------------------------
// Stage A: H = relu(Xg @ w1_l + b1_l). grid (8, 512, 4), early-exit on
// d/count. A-rows gathered by bucket; H stored by token id (ld=1024).
// ---------------------------------------------------------------------------
__global__ __launch_bounds__(256, 2) void stageA_kernel(CompParams P) {
    const int lev = blockIdx.z;
    const int d = HD >> lev;
    const int n0 = blockIdx.x * 128;
    if (n0 >= d) return;
    const int cnt = g_count[lev];
    const int m0 = blockIdx.y * 128;
    if (m0 >= cnt) return;

    __shared__ float As[8][128], Bs[8][128];
    const int tid = threadIdx.x;
    const int rowA = tid & 127, kA = (tid >> 7) << 2;
    int rload = m0 + rowA; if (rload > cnt - 1) rload = cnt - 1;
    const int tl = g_idx[lev * TOK_TOTAL + rload];
    const float* arow = (tl < TOK_HALF)
        ? (P.keys + (size_t)tl * HD)
        : (P.values + (size_t)(tl - TOK_HALF) * HD);

    float c[8][8];
#pragma unroll
    for (int i = 0; i < 8; i++)
#pragma unroll
        for (int j = 0; j < 8; j++) c[i][j] = 0.f;

    gemm_mainloop(arow + kA, P.w1[lev] + n0, d, HD, c, As, Bs);

    const int tx = tid & 15, ty = tid >> 4;
    const float* b1 = P.b1[lev] + n0;
    float b1v[8];
#pragma unroll
    for (int j = 0; j < 8; j++) b1v[j] = b1[cmap(tx, j)];

#pragma unroll
    for (int i = 0; i < 8; i++) {
        int r = m0 + rmap(ty, i);
        if (r < cnt) {
            int t = g_idx[lev * TOK_TOTAL + r];
            float* dst = g_H + (size_t)t * HD + n0;
            float4 v0, v1;
            v0.x = fmaxf(c[i][0] + b1v[0], 0.f);
            v0.y = fmaxf(c[i][1] + b1v[1], 0.f);
            v0.z = fmaxf(c[i][2] + b1v[2], 0.f);
            v0.w = fmaxf(c[i][3] + b1v[3], 0.f);
            v1.x = fmaxf(c[i][4] + b1v[4], 0.f);
            v1.y = fmaxf(c[i][5] + b1v[5], 0.f);
            v1.z = fmaxf(c[i][6] + b1v[6], 0.f);
            v1.w = fmaxf(c[i][7] + b1v[7], 0.f);
            *(float4*)(dst + tx * 4)      = v0;
            *(float4*)(dst + 64 + tx * 4) = v1;
        }
    }
}

// ---------------------------------------------------------------------------
// Stage B: out = H @ w2_l + b2_l, scattered to out rows by token id.
// out layout: [keys_out | values_out] -> token t maps to out + t*1024.
// ---------------------------------------------------------------------------
__global__ __launch_bounds__(256, 2) void stageB_kernel(CompParams P) {
    const int lev = blockIdx.z;
    const int d = HD >> lev;               // K dimension
    const int n0 = blockIdx.x * 128;       // N = 1024
    const int cnt = g_count[lev];
    const int m0 = blockIdx.y * 128;
    if (m0 >= cnt) return;

    __shared__ float As[8][128], Bs[8][128];
    const int tid = threadIdx.x;
    const int rowA = tid & 127, kA = (tid >> 7) << 2;
    int rload = m0 + rowA; if (rload > cnt - 1) rload = cnt - 1;
    const int tl = g_idx[lev * TOK_TOTAL + rload];

    float c[8][8];
#pragma unroll
    for (int i = 0; i < 8; i++)
#pragma unroll
        for (int j = 0; j < 8; j++) c[i][j] = 0.f;

    gemm_mainloop(g_H + (size_t)tl * HD + kA, P.w2[lev] + n0, HD, d, c, As, Bs);

    const int tx = tid & 15, ty = tid >> 4;
    const float* b2 = P.b2[lev] + n0;
    float b2v[8];
#pragma unroll
    for (int j = 0; j < 8; j++) b2v[j] = b2[cmap(tx, j)];

#pragma unroll
    for (int i = 0; i < 8; i++) {
        int r = m0 + rmap(ty, i);
        if (r < cnt) {
            int t = g_idx[lev * TOK_TOTAL + r];
            float* dst = P.out + (size_t)t * HD + n0;
            float4 v0, v1;
            v0.x = c[i][0] + b2v[0];
            v0.y = c[i][1] + b2v[1];
            v0.z = c[i][2] + b2v[2];
            v0.w = c[i][3] + b2v[3];
            v1.x = c[i][4] + b2v[4];
            v1.y = c[i][5] + b2v[5];
            v1.z = c[i][6] + b2v[6];
            v1.w = c[i][7] + b2v[7];
            *(float4*)(dst + tx * 4)      = v0;
            *(float4*)(dst + 64 + tx * 4) = v1;
        }
    }
}

// ---------------------------------------------------------------------------
extern "C" void kernel_launch(void* const* d_in, const int* in_sizes, int n_in,
                              void* d_out, int out_size) {
    const float* keys   = (const float*)d_in[0];
    const float* values = (const float*)d_in[1];
    const float* Pw1    = (const float*)d_in[2];
    const float* Pb1    = (const float*)d_in[3];
    const float* Pw2    = (const float*)d_in[4];
    const float* Pb2    = (const float*)d_in[5];

    CompParams P;
    P.keys = keys; P.values = values;
    for (int l = 0; l < 4; l++) {
        P.w1[l] = (const float*)d_in[6 + l * 4 + 0];
        P.b1[l] = (const float*)d_in[6 + l * 4 + 1];
        P.w2[l] = (const float*)d_in[6 + l * 4 + 2];
        P.b2[l] = (const float*)d_in[6 + l * 4 + 3];
    }
    P.out = (float*)d_out;

    zero_kernel<<<(TOK_TOTAL * NLEV + 255) / 256, 256>>>();

    dim3 pgrid(8, 256, 2);                 // N-tiles, M-tiles (32768/128), keys|values
    predictor_kernel<<<pgrid, 256>>>(keys, values, Pw1, Pb1, Pw2);

    argmax_kernel<<<TOK_TOTAL / 256, 256>>>(Pb2);

    dim3 cgrid(8, 512, 4);                 // N-tiles, M-tiles (65536/128), levels
    stageA_kernel<<<cgrid, 256>>>(P);
    stageB_kernel<<<cgrid, 256>>>(P);
}